// round 1
// baseline (speedup 1.0000x reference)
#include <cuda_runtime.h>
#include <math.h>

#define Bb   2
#define Tt   2048
#define ROWS (Bb*Tt)     // 4096
#define PW   1536        // packed width: q|k0|k1|v0|v1|gate

// ---------------- scratch (static device globals; no runtime alloc) ----------------
__device__ float g_Wpack[256 * PW];              // 1.5 MB
__device__ float g_pack[(size_t)ROWS * PW];      // 25.2 MB packed projections
__device__ float g_qn [ROWS * 256];              // normed q
__device__ float g_k0n[ROWS * 256];              // normed k (j=0)
__device__ float g_k1n[ROWS * 256];              // normed k (j=1)
__device__ float g_v  [ROWS * 2 * 256];          // silu'd v (j=0,1)
__device__ float g_beta[ROWS * 2];
__device__ float g_g  [ROWS];
__device__ float g_cc [ROWS * 3];                // c10=k0·k1, cq0=q·k0, cq1=q·k1
__device__ float g_o  [ROWS * 256];              // scan output, gated in place

// ---------------- weight packing: [256][1536] ----------------
__global__ void pack_weights(const float* __restrict__ Wq, const float* __restrict__ Wk,
                             const float* __restrict__ Wv, const float* __restrict__ Wg)
{
    int d = blockIdx.x, c = threadIdx.x;
    g_Wpack[d*PW + c]        = Wq[d*256 + c];
    g_Wpack[d*PW + 256 + c]  = Wk[d*256 + c];
    g_Wpack[d*PW + 512 + c]  = Wk[65536 + d*256 + c];
    g_Wpack[d*PW + 768 + c]  = Wv[d*256 + c];
    g_Wpack[d*PW + 1024 + c] = Wv[65536 + d*256 + c];
    g_Wpack[d*PW + 1280 + c] = Wg[d*256 + c];
}

// ---------------- fp32 tiled GEMM: C[M,N] = A[M,256] * B[256,N] ----------------
// 64x64 tile, 256 threads, 4x4 microtile, K fixed = 256
__global__ __launch_bounds__(256)
void gemm_kernel(const float* __restrict__ A, const float* __restrict__ B,
                 float* __restrict__ C, int lda, int ldb, int ldc)
{
    __shared__ float As[32][68];   // transposed A tile, padded
    __shared__ float Bs[32][64];
    int bm = blockIdx.x * 64, bn = blockIdx.y * 64;
    int tid = threadIdx.x;
    int tx = tid & 15, ty = tid >> 4;
    float acc[4][4] = {};
    for (int k0 = 0; k0 < 256; k0 += 32) {
        #pragma unroll
        for (int i = 0; i < 2; i++) {
            int idx = tid + i*256;
            int ar = idx >> 3, ac = (idx & 7) << 2;
            float4 av = *(const float4*)(A + (size_t)(bm+ar)*lda + k0 + ac);
            As[ac+0][ar] = av.x; As[ac+1][ar] = av.y;
            As[ac+2][ar] = av.z; As[ac+3][ar] = av.w;
            int br = idx >> 4, bc = (idx & 15) << 2;
            *(float4*)(&Bs[br][bc]) = *(const float4*)(B + (size_t)(k0+br)*ldb + bn + bc);
        }
        __syncthreads();
        #pragma unroll
        for (int k = 0; k < 32; k++) {
            float a[4], b[4];
            *(float4*)a = *(const float4*)(&As[k][ty<<2]);
            *(float4*)b = *(const float4*)(&Bs[k][tx<<2]);
            #pragma unroll
            for (int i = 0; i < 4; i++)
                #pragma unroll
                for (int j = 0; j < 4; j++)
                    acc[i][j] = fmaf(a[i], b[j], acc[i][j]);
        }
        __syncthreads();
    }
    #pragma unroll
    for (int i = 0; i < 4; i++)
        *(float4*)(C + (size_t)(bm + (ty<<2) + i)*ldc + bn + (tx<<2)) = *(float4*)acc[i];
}

// ---------------- beta / g projections (small GEMVs) ----------------
__global__ void proj_small(const float* __restrict__ x, const float* __restrict__ Wb,
                           const float* __restrict__ Wa, const float* __restrict__ A_log,
                           const float* __restrict__ dt_bias)
{
    int row  = blockIdx.x * 4 + (threadIdx.x >> 5);
    int lane = threadIdx.x & 31;
    const float* xr = x + (size_t)row * 256;
    float a0 = 0.f, a1 = 0.f, a2 = 0.f;
    #pragma unroll
    for (int r = 0; r < 8; r++) {
        int d = lane + 32*r;
        float xv = xr[d];
        a0 = fmaf(xv, Wb[d],       a0);
        a1 = fmaf(xv, Wb[256 + d], a1);
        a2 = fmaf(xv, Wa[d],       a2);
    }
    #pragma unroll
    for (int off = 16; off; off >>= 1) {
        a0 += __shfl_xor_sync(0xffffffffu, a0, off);
        a1 += __shfl_xor_sync(0xffffffffu, a1, off);
        a2 += __shfl_xor_sync(0xffffffffu, a2, off);
    }
    if (lane == 0) {
        g_beta[row*2 + 0] = 1.f / (1.f + expf(-a0));
        g_beta[row*2 + 1] = 1.f / (1.f + expf(-a1));
        float z  = a2 + dt_bias[0];
        float sp = (z > 20.f) ? z : log1pf(expf(z));
        g_g[row] = -expf(A_log[0]) * sp;
    }
}

// ---------------- causal conv4 + silu + l2norm + per-step dot scalars ----------------
__global__ __launch_bounds__(256)
void conv_norm_kernel(const float* __restrict__ qw, const float* __restrict__ kw,
                      const float* __restrict__ vw)
{
    int row = blockIdx.x;
    int t   = row & (Tt - 1);
    int c   = threadIdx.x;
    int lane = c & 31, w = c >> 5;
    float acc[5] = {0.f, 0.f, 0.f, 0.f, 0.f};
    #pragma unroll
    for (int i = 0; i < 4; i++) {
        if (t - 3 + i < 0) continue;
        const float* Pr = g_pack + (size_t)(row - 3 + i) * PW;
        acc[0] = fmaf(Pr[c],        qw[c*4 + i],          acc[0]);
        acc[1] = fmaf(Pr[256 + c],  kw[c*4 + i],          acc[1]);
        acc[2] = fmaf(Pr[512 + c],  kw[(256 + c)*4 + i],  acc[2]);
        acc[3] = fmaf(Pr[768 + c],  vw[c*4 + i],          acc[3]);
        acc[4] = fmaf(Pr[1024 + c], vw[(256 + c)*4 + i],  acc[4]);
    }
    #pragma unroll
    for (int m = 0; m < 5; m++) acc[m] = acc[m] / (1.f + expf(-acc[m]));  // silu

    __shared__ float red[3][8];
    // phase 1: sum of squares for q, k0, k1
    float r0 = acc[0]*acc[0], r1 = acc[1]*acc[1], r2 = acc[2]*acc[2];
    #pragma unroll
    for (int off = 16; off; off >>= 1) {
        r0 += __shfl_xor_sync(0xffffffffu, r0, off);
        r1 += __shfl_xor_sync(0xffffffffu, r1, off);
        r2 += __shfl_xor_sync(0xffffffffu, r2, off);
    }
    if (lane == 0) { red[0][w] = r0; red[1][w] = r1; red[2][w] = r2; }
    __syncthreads();
    float s0 = 0.f, s1 = 0.f, s2 = 0.f;
    #pragma unroll
    for (int i = 0; i < 8; i++) { s0 += red[0][i]; s1 += red[1][i]; s2 += red[2][i]; }
    float qv  = acc[0] * rsqrtf(s0 + 1e-6f);
    float k0v = acc[1] * rsqrtf(s1 + 1e-6f);
    float k1v = acc[2] * rsqrtf(s2 + 1e-6f);
    __syncthreads();
    // phase 2: cross dots c10 = k0·k1, cq0 = q·k0, cq1 = q·k1
    r0 = k0v * k1v; r1 = qv * k0v; r2 = qv * k1v;
    #pragma unroll
    for (int off = 16; off; off >>= 1) {
        r0 += __shfl_xor_sync(0xffffffffu, r0, off);
        r1 += __shfl_xor_sync(0xffffffffu, r1, off);
        r2 += __shfl_xor_sync(0xffffffffu, r2, off);
    }
    if (lane == 0) { red[0][w] = r0; red[1][w] = r1; red[2][w] = r2; }
    __syncthreads();
    s0 = 0.f; s1 = 0.f; s2 = 0.f;
    #pragma unroll
    for (int i = 0; i < 8; i++) { s0 += red[0][i]; s1 += red[1][i]; s2 += red[2][i]; }
    if (c == 0) { g_cc[row*3 + 0] = s0; g_cc[row*3 + 1] = s1; g_cc[row*3 + 2] = s2; }

    g_qn [row*256 + c] = qv;
    g_k0n[row*256 + c] = k0v;
    g_k1n[row*256 + c] = k1v;
    g_v[(size_t)(row*2 + 0)*256 + c] = acc[3];
    g_v[(size_t)(row*2 + 1)*256 + c] = acc[4];
}

// ---------------- the scan: 1 warp per value-column, 8 cols/CTA, grid (32, B) -------
// State S[:,v] in 8 regs/lane (lane owns d = lane+32r). Per step, rank-2 fused form:
//   m0=k0·S, m1=k1·S, mq=q·S   (3 interleaved warp reductions, one latency)
//   u0 = b0*(v0 - eg*m0)
//   u1 = b1*(v1 - eg*m1 - (k0·k1)*u0)
//   o  = eg*mq + (q·k0)*u0 + (q·k1)*u1
//   S  = eg*S + u0*k0 + u1*k1
__global__ __launch_bounds__(256)
void scan_kernel()
{
    int b    = blockIdx.y;
    int cb   = blockIdx.x * 8;
    int tid  = threadIdx.x;
    int warp = tid >> 5, lane = tid & 31;
    int col  = cb + warp;
    __shared__ float buf[2][792];
    // buffer layout: [0:256) q, [256:512) k0, [512:768) k1,
    // [768:776) v0 cols, [776:784) v1 cols, 784 eg, 785 b0, 786 b1, 787 c10, 788 cq0, 789 cq1
    int base = b * Tt;

    { // preload step 0
        int row = base;
        buf[0][tid]       = g_qn [row*256 + tid];
        buf[0][256 + tid] = g_k0n[row*256 + tid];
        buf[0][512 + tid] = g_k1n[row*256 + tid];
        float px = 0.f;
        if      (tid < 8)   px = g_v[(size_t)(row*2)*256 + cb + tid];
        else if (tid < 16)  px = g_v[(size_t)(row*2 + 1)*256 + cb + (tid - 8)];
        else if (tid == 16) px = g_g[row];
        else if (tid == 17) px = g_beta[row*2];
        else if (tid == 18) px = g_beta[row*2 + 1];
        else if (tid < 22)  px = g_cc[row*3 + (tid - 19)];
        if (tid < 22) buf[0][768 + tid] = (tid == 16) ? expf(px) : px;
    }
    __syncthreads();

    float s[8];
    #pragma unroll
    for (int r = 0; r < 8; r++) s[r] = 0.f;

    for (int t = 0; t < Tt; t++) {
        int cur = t & 1;
        // prefetch step t+1 into registers (overlaps with compute below)
        int tn   = (t + 1 < Tt) ? (t + 1) : t;
        int nrow = base + tn;
        float pq  = g_qn [nrow*256 + tid];
        float pk0 = g_k0n[nrow*256 + tid];
        float pk1 = g_k1n[nrow*256 + tid];
        float px = 0.f;
        if      (tid < 8)   px = g_v[(size_t)(nrow*2)*256 + cb + tid];
        else if (tid < 16)  px = g_v[(size_t)(nrow*2 + 1)*256 + cb + (tid - 8)];
        else if (tid == 16) px = g_g[nrow];
        else if (tid == 17) px = g_beta[nrow*2];
        else if (tid == 18) px = g_beta[nrow*2 + 1];
        else if (tid < 22)  px = g_cc[nrow*3 + (tid - 19)];

        const float* bc = buf[cur];
        float eg  = bc[784];
        float b0  = bc[785], b1  = bc[786];
        float c10 = bc[787], cq0 = bc[788], cq1 = bc[789];
        float v0  = bc[768 + warp], v1 = bc[776 + warp];

        float kr0[8], kr1[8];
        float m0a = 0.f, m0b = 0.f, m1a = 0.f, m1b = 0.f, mqa = 0.f, mqb = 0.f;
        #pragma unroll
        for (int r = 0; r < 8; r += 2) {
            kr0[r]   = bc[256 + lane + 32*r];
            kr0[r+1] = bc[256 + lane + 32*(r+1)];
            kr1[r]   = bc[512 + lane + 32*r];
            kr1[r+1] = bc[512 + lane + 32*(r+1)];
            float q0 = bc[lane + 32*r];
            float q1 = bc[lane + 32*(r+1)];
            m0a = fmaf(s[r],   kr0[r],   m0a);  m0b = fmaf(s[r+1], kr0[r+1], m0b);
            m1a = fmaf(s[r],   kr1[r],   m1a);  m1b = fmaf(s[r+1], kr1[r+1], m1b);
            mqa = fmaf(s[r],   q0,       mqa);  mqb = fmaf(s[r+1], q1,       mqb);
        }
        float m0 = m0a + m0b, m1 = m1a + m1b, mq = mqa + mqb;
        #pragma unroll
        for (int off = 16; off; off >>= 1) {
            m0 += __shfl_xor_sync(0xffffffffu, m0, off);
            m1 += __shfl_xor_sync(0xffffffffu, m1, off);
            mq += __shfl_xor_sync(0xffffffffu, mq, off);
        }
        float u0 = b0 * fmaf(-eg, m0, v0);
        float u1 = b1 * (v1 - eg*m1 - c10*u0);
        float ov = fmaf(eg, mq, fmaf(cq0, u0, cq1*u1));
        #pragma unroll
        for (int r = 0; r < 8; r++)
            s[r] = fmaf(kr1[r], u1, fmaf(kr0[r], u0, eg * s[r]));
        if (lane == 0) g_o[(size_t)(base + t)*256 + col] = ov;

        // stage prefetched step into the other buffer
        float* bn2 = buf[cur ^ 1];
        bn2[tid]       = pq;
        bn2[256 + tid] = pk0;
        bn2[512 + tid] = pk1;
        if (tid < 22) bn2[768 + tid] = (tid == 16) ? expf(px) : px;
        __syncthreads();
    }
}

// ---------------- output rms-norm * o_norm_w * silu(gate), in place ----------------
__global__ __launch_bounds__(256)
void gate_kernel(const float* __restrict__ onw)
{
    int row = blockIdx.x, c = threadIdx.x;
    int lane = c & 31, w = c >> 5;
    float ov = g_o[(size_t)row*256 + c];
    float r = ov * ov;
    __shared__ float red[8];
    #pragma unroll
    for (int off = 16; off; off >>= 1) r += __shfl_xor_sync(0xffffffffu, r, off);
    if (lane == 0) red[w] = r;
    __syncthreads();
    float sum = 0.f;
    #pragma unroll
    for (int i = 0; i < 8; i++) sum += red[i];
    float gt  = g_pack[(size_t)row*PW + 1280 + c];
    float res = ov * rsqrtf(sum * (1.f/256.f) + 1e-5f) * onw[c] * (gt / (1.f + expf(-gt)));
    g_o[(size_t)row*256 + c] = res;
}

// ---------------- launch ----------------
extern "C" void kernel_launch(void* const* d_in, const int* in_sizes, int n_in,
                              void* d_out, int out_size)
{
    const float* x       = (const float*)d_in[0];
    const float* Wq      = (const float*)d_in[1];
    const float* Wk      = (const float*)d_in[2];
    const float* Wv      = (const float*)d_in[3];
    const float* Wb      = (const float*)d_in[4];
    const float* Wa      = (const float*)d_in[5];
    const float* A_log   = (const float*)d_in[6];
    const float* dt_bias = (const float*)d_in[7];
    const float* qcw     = (const float*)d_in[8];
    const float* kcw     = (const float*)d_in[9];
    const float* vcw     = (const float*)d_in[10];
    const float* Wg      = (const float*)d_in[11];
    const float* onw     = (const float*)d_in[12];
    const float* Wo      = (const float*)d_in[13];
    float* out = (float*)d_out;

    float *pWpack, *pPack, *pO;
    cudaGetSymbolAddress((void**)&pWpack, g_Wpack);
    cudaGetSymbolAddress((void**)&pPack,  g_pack);
    cudaGetSymbolAddress((void**)&pO,     g_o);

    pack_weights<<<256, 256>>>(Wq, Wk, Wv, Wg);
    proj_small<<<ROWS/4, 128>>>(x, Wb, Wa, A_log, dt_bias);
    gemm_kernel<<<dim3(ROWS/64, PW/64), 256>>>(x, pWpack, pPack, 256, PW, PW);
    conv_norm_kernel<<<ROWS, 256>>>(qcw, kcw, vcw);
    scan_kernel<<<dim3(32, Bb), 256>>>();
    gate_kernel<<<ROWS, 256>>>(onw);
    gemm_kernel<<<dim3(ROWS/64, 256/64), 256>>>(pO, Wo, out, 256, 256, 256);
}

// round 2
// speedup vs baseline: 2.3247x; 2.3247x over previous
#include <cuda_runtime.h>
#include <math.h>

#define Bb   2
#define Tt   2048
#define ROWS (Bb*Tt)     // 4096
#define PW   1536        // packed width: q|k0|k1|v0|v1|gate

// ---------------- scratch (static device globals; no runtime alloc) ----------------
__device__ float g_Wpack[256 * PW];              // 1.5 MB
__device__ float g_pack[(size_t)ROWS * PW];      // 25.2 MB packed projections
__device__ float g_qn [ROWS * 256];              // normed q
__device__ float g_k0n[ROWS * 256];              // normed k (j=0)
__device__ float g_k1n[ROWS * 256];              // normed k (j=1)
__device__ float g_v  [ROWS * 2 * 256];          // silu'd v (j=0,1)
__device__ float g_sc [ROWS * 8];                // per-step scalars: eg,b0,b1,c10,cq0,cq1,-,-
__device__ float g_o  [ROWS * 256];              // scan output, gated in place

// ---------------- weight packing: [256][1536] ----------------
__global__ void pack_weights(const float* __restrict__ Wq, const float* __restrict__ Wk,
                             const float* __restrict__ Wv, const float* __restrict__ Wg)
{
    int d = blockIdx.x, c = threadIdx.x;
    g_Wpack[d*PW + c]        = Wq[d*256 + c];
    g_Wpack[d*PW + 256 + c]  = Wk[d*256 + c];
    g_Wpack[d*PW + 512 + c]  = Wk[65536 + d*256 + c];
    g_Wpack[d*PW + 768 + c]  = Wv[d*256 + c];
    g_Wpack[d*PW + 1024 + c] = Wv[65536 + d*256 + c];
    g_Wpack[d*PW + 1280 + c] = Wg[d*256 + c];
}

// ---------------- fp32 tiled GEMM: C[M,N] = A[M,256] * B[256,N] ----------------
__global__ __launch_bounds__(256)
void gemm_kernel(const float* __restrict__ A, const float* __restrict__ B,
                 float* __restrict__ C, int lda, int ldb, int ldc)
{
    __shared__ float As[32][68];
    __shared__ float Bs[32][64];
    int bm = blockIdx.x * 64, bn = blockIdx.y * 64;
    int tid = threadIdx.x;
    int tx = tid & 15, ty = tid >> 4;
    float acc[4][4] = {};
    for (int k0 = 0; k0 < 256; k0 += 32) {
        #pragma unroll
        for (int i = 0; i < 2; i++) {
            int idx = tid + i*256;
            int ar = idx >> 3, ac = (idx & 7) << 2;
            float4 av = *(const float4*)(A + (size_t)(bm+ar)*lda + k0 + ac);
            As[ac+0][ar] = av.x; As[ac+1][ar] = av.y;
            As[ac+2][ar] = av.z; As[ac+3][ar] = av.w;
            int br = idx >> 4, bc = (idx & 15) << 2;
            *(float4*)(&Bs[br][bc]) = *(const float4*)(B + (size_t)(k0+br)*ldb + bn + bc);
        }
        __syncthreads();
        #pragma unroll
        for (int k = 0; k < 32; k++) {
            float a[4], b[4];
            *(float4*)a = *(const float4*)(&As[k][ty<<2]);
            *(float4*)b = *(const float4*)(&Bs[k][tx<<2]);
            #pragma unroll
            for (int i = 0; i < 4; i++)
                #pragma unroll
                for (int j = 0; j < 4; j++)
                    acc[i][j] = fmaf(a[i], b[j], acc[i][j]);
        }
        __syncthreads();
    }
    #pragma unroll
    for (int i = 0; i < 4; i++)
        *(float4*)(C + (size_t)(bm + (ty<<2) + i)*ldc + bn + (tx<<2)) = *(float4*)acc[i];
}

// ---------------- beta / g projections -> packed scalar record ----------------
__global__ void proj_small(const float* __restrict__ x, const float* __restrict__ Wb,
                           const float* __restrict__ Wa, const float* __restrict__ A_log,
                           const float* __restrict__ dt_bias)
{
    int row  = blockIdx.x * 4 + (threadIdx.x >> 5);
    int lane = threadIdx.x & 31;
    const float* xr = x + (size_t)row * 256;
    float a0 = 0.f, a1 = 0.f, a2 = 0.f;
    #pragma unroll
    for (int r = 0; r < 8; r++) {
        int d = lane + 32*r;
        float xv = xr[d];
        a0 = fmaf(xv, Wb[d],       a0);
        a1 = fmaf(xv, Wb[256 + d], a1);
        a2 = fmaf(xv, Wa[d],       a2);
    }
    #pragma unroll
    for (int off = 16; off; off >>= 1) {
        a0 += __shfl_xor_sync(0xffffffffu, a0, off);
        a1 += __shfl_xor_sync(0xffffffffu, a1, off);
        a2 += __shfl_xor_sync(0xffffffffu, a2, off);
    }
    if (lane == 0) {
        float z  = a2 + dt_bias[0];
        float sp = (z > 20.f) ? z : log1pf(expf(z));
        float g  = -expf(A_log[0]) * sp;
        g_sc[row*8 + 0] = expf(g);                 // eg, precomputed
        g_sc[row*8 + 1] = 1.f / (1.f + expf(-a0)); // b0
        g_sc[row*8 + 2] = 1.f / (1.f + expf(-a1)); // b1
    }
}

// ---------------- causal conv4 + silu + l2norm + per-step dot scalars ----------------
__global__ __launch_bounds__(256)
void conv_norm_kernel(const float* __restrict__ qw, const float* __restrict__ kw,
                      const float* __restrict__ vw)
{
    int row = blockIdx.x;
    int t   = row & (Tt - 1);
    int c   = threadIdx.x;
    int lane = c & 31, w = c >> 5;
    float acc[5] = {0.f, 0.f, 0.f, 0.f, 0.f};
    #pragma unroll
    for (int i = 0; i < 4; i++) {
        if (t - 3 + i < 0) continue;
        const float* Pr = g_pack + (size_t)(row - 3 + i) * PW;
        acc[0] = fmaf(Pr[c],        qw[c*4 + i],          acc[0]);
        acc[1] = fmaf(Pr[256 + c],  kw[c*4 + i],          acc[1]);
        acc[2] = fmaf(Pr[512 + c],  kw[(256 + c)*4 + i],  acc[2]);
        acc[3] = fmaf(Pr[768 + c],  vw[c*4 + i],          acc[3]);
        acc[4] = fmaf(Pr[1024 + c], vw[(256 + c)*4 + i],  acc[4]);
    }
    #pragma unroll
    for (int m = 0; m < 5; m++) acc[m] = acc[m] / (1.f + expf(-acc[m]));  // silu

    __shared__ float red[3][8];
    float r0 = acc[0]*acc[0], r1 = acc[1]*acc[1], r2 = acc[2]*acc[2];
    #pragma unroll
    for (int off = 16; off; off >>= 1) {
        r0 += __shfl_xor_sync(0xffffffffu, r0, off);
        r1 += __shfl_xor_sync(0xffffffffu, r1, off);
        r2 += __shfl_xor_sync(0xffffffffu, r2, off);
    }
    if (lane == 0) { red[0][w] = r0; red[1][w] = r1; red[2][w] = r2; }
    __syncthreads();
    float s0 = 0.f, s1 = 0.f, s2 = 0.f;
    #pragma unroll
    for (int i = 0; i < 8; i++) { s0 += red[0][i]; s1 += red[1][i]; s2 += red[2][i]; }
    float qv  = acc[0] * rsqrtf(s0 + 1e-6f);
    float k0v = acc[1] * rsqrtf(s1 + 1e-6f);
    float k1v = acc[2] * rsqrtf(s2 + 1e-6f);
    __syncthreads();
    r0 = k0v * k1v; r1 = qv * k0v; r2 = qv * k1v;
    #pragma unroll
    for (int off = 16; off; off >>= 1) {
        r0 += __shfl_xor_sync(0xffffffffu, r0, off);
        r1 += __shfl_xor_sync(0xffffffffu, r1, off);
        r2 += __shfl_xor_sync(0xffffffffu, r2, off);
    }
    if (lane == 0) { red[0][w] = r0; red[1][w] = r1; red[2][w] = r2; }
    __syncthreads();
    s0 = 0.f; s1 = 0.f; s2 = 0.f;
    #pragma unroll
    for (int i = 0; i < 8; i++) { s0 += red[0][i]; s1 += red[1][i]; s2 += red[2][i]; }
    if (c == 0) { g_sc[row*8 + 3] = s0; g_sc[row*8 + 4] = s1; g_sc[row*8 + 5] = s2; }

    g_qn [row*256 + c] = qv;
    g_k0n[row*256 + c] = k0v;
    g_k1n[row*256 + c] = k1v;
    g_v[(size_t)(row*2 + 0)*256 + c] = acc[3];
    g_v[(size_t)(row*2 + 1)*256 + c] = acc[4];
}

// ---------------- scan: 1 warp = 1 value-column, no smem, no syncthreads ----------
// Lane owns d = lane*8..lane*8+7 of the state column (8 regs). Per step:
//   m0=k0·S, m1=k1·S, mq=q·S   (3 interleaved shuffle reductions)
//   u0 = b0*(v0 - eg*m0)
//   u1 = b1*(v1 - eg*m1 - (k0·k1)*u0)
//   o  = eg*mq + (q·k0)*u0 + (q·k1)*u1
//   S  = eg*S + u0*k0 + u1*k1
// q/k rows double-buffered in registers (prefetch distance 1). The 4 warps of a
// CTA read the same rows -> L1 serves 3/4 of the traffic.
#define LOAD_STEP(sl, row) do {                                                   \
    size_t _o = (size_t)(row)*256 + lane*8;                                       \
    float4 _a, _b;                                                                \
    _a = *(const float4*)(g_qn + _o); _b = *(const float4*)(g_qn + _o + 4);       \
    q[sl][0]=_a.x; q[sl][1]=_a.y; q[sl][2]=_a.z; q[sl][3]=_a.w;                   \
    q[sl][4]=_b.x; q[sl][5]=_b.y; q[sl][6]=_b.z; q[sl][7]=_b.w;                   \
    _a = *(const float4*)(g_k0n + _o); _b = *(const float4*)(g_k0n + _o + 4);     \
    k0[sl][0]=_a.x; k0[sl][1]=_a.y; k0[sl][2]=_a.z; k0[sl][3]=_a.w;               \
    k0[sl][4]=_b.x; k0[sl][5]=_b.y; k0[sl][6]=_b.z; k0[sl][7]=_b.w;               \
    _a = *(const float4*)(g_k1n + _o); _b = *(const float4*)(g_k1n + _o + 4);     \
    k1[sl][0]=_a.x; k1[sl][1]=_a.y; k1[sl][2]=_a.z; k1[sl][3]=_a.w;               \
    k1[sl][4]=_b.x; k1[sl][5]=_b.y; k1[sl][6]=_b.z; k1[sl][7]=_b.w;               \
    scA[sl] = *(const float4*)(g_sc + (size_t)(row)*8);                           \
    scB[sl] = *(const float4*)(g_sc + (size_t)(row)*8 + 4);                       \
    vv0[sl] = g_v[(size_t)(row)*512 + col];                                       \
    vv1[sl] = g_v[(size_t)(row)*512 + 256 + col];                                 \
} while (0)

__global__ __launch_bounds__(128)
void scan_kernel()
{
    int b    = blockIdx.y;
    int warp = threadIdx.x >> 5, lane = threadIdx.x & 31;
    int col  = blockIdx.x * 4 + warp;   // 0..255
    int base = b * Tt;

    float s[8];
    #pragma unroll
    for (int r = 0; r < 8; r++) s[r] = 0.f;

    float q[2][8], k0[2][8], k1[2][8];
    float4 scA[2], scB[2];
    float vv0[2], vv1[2];

    LOAD_STEP(0, base);

    #pragma unroll 2
    for (int t = 0; t < Tt; t++) {
        int cur = t & 1, nxt = cur ^ 1;
        int nrow = base + ((t + 1 < Tt) ? (t + 1) : t);
        LOAD_STEP(nxt, nrow);    // prefetch next step (overlaps compute below)

        float m0a = 0.f, m0b = 0.f, m1a = 0.f, m1b = 0.f, mqa = 0.f, mqb = 0.f;
        #pragma unroll
        for (int r = 0; r < 8; r += 2) {
            m0a = fmaf(s[r],   k0[cur][r],   m0a);
            m0b = fmaf(s[r+1], k0[cur][r+1], m0b);
            m1a = fmaf(s[r],   k1[cur][r],   m1a);
            m1b = fmaf(s[r+1], k1[cur][r+1], m1b);
            mqa = fmaf(s[r],   q[cur][r],    mqa);
            mqb = fmaf(s[r+1], q[cur][r+1],  mqb);
        }
        float m0 = m0a + m0b, m1 = m1a + m1b, mq = mqa + mqb;
        #pragma unroll
        for (int off = 16; off; off >>= 1) {
            m0 += __shfl_xor_sync(0xffffffffu, m0, off);
            m1 += __shfl_xor_sync(0xffffffffu, m1, off);
            mq += __shfl_xor_sync(0xffffffffu, mq, off);
        }
        float eg  = scA[cur].x, b0 = scA[cur].y, b1 = scA[cur].z, c10 = scA[cur].w;
        float cq0 = scB[cur].x, cq1 = scB[cur].y;
        float u0 = b0 * fmaf(-eg, m0, vv0[cur]);
        float u1 = b1 * (vv1[cur] - eg*m1 - c10*u0);
        float ov = fmaf(eg, mq, fmaf(cq0, u0, cq1*u1));
        #pragma unroll
        for (int r = 0; r < 8; r++)
            s[r] = fmaf(k1[cur][r], u1, fmaf(k0[cur][r], u0, eg * s[r]));
        if (lane == 0) g_o[(size_t)(base + t)*256 + col] = ov;
    }
}

// ---------------- output rms-norm * o_norm_w * silu(gate), in place ----------------
__global__ __launch_bounds__(256)
void gate_kernel(const float* __restrict__ onw)
{
    int row = blockIdx.x, c = threadIdx.x;
    int lane = c & 31, w = c >> 5;
    float ov = g_o[(size_t)row*256 + c];
    float r = ov * ov;
    __shared__ float red[8];
    #pragma unroll
    for (int off = 16; off; off >>= 1) r += __shfl_xor_sync(0xffffffffu, r, off);
    if (lane == 0) red[w] = r;
    __syncthreads();
    float sum = 0.f;
    #pragma unroll
    for (int i = 0; i < 8; i++) sum += red[i];
    float gt  = g_pack[(size_t)row*PW + 1280 + c];
    float res = ov * rsqrtf(sum * (1.f/256.f) + 1e-5f) * onw[c] * (gt / (1.f + expf(-gt)));
    g_o[(size_t)row*256 + c] = res;
}

// ---------------- launch ----------------
extern "C" void kernel_launch(void* const* d_in, const int* in_sizes, int n_in,
                              void* d_out, int out_size)
{
    const float* x       = (const float*)d_in[0];
    const float* Wq      = (const float*)d_in[1];
    const float* Wk      = (const float*)d_in[2];
    const float* Wv      = (const float*)d_in[3];
    const float* Wb      = (const float*)d_in[4];
    const float* Wa      = (const float*)d_in[5];
    const float* A_log   = (const float*)d_in[6];
    const float* dt_bias = (const float*)d_in[7];
    const float* qcw     = (const float*)d_in[8];
    const float* kcw     = (const float*)d_in[9];
    const float* vcw     = (const float*)d_in[10];
    const float* Wg      = (const float*)d_in[11];
    const float* onw     = (const float*)d_in[12];
    const float* Wo      = (const float*)d_in[13];
    float* out = (float*)d_out;

    float *pWpack, *pPack, *pO;
    cudaGetSymbolAddress((void**)&pWpack, g_Wpack);
    cudaGetSymbolAddress((void**)&pPack,  g_pack);
    cudaGetSymbolAddress((void**)&pO,     g_o);

    pack_weights<<<256, 256>>>(Wq, Wk, Wv, Wg);
    proj_small<<<ROWS/4, 128>>>(x, Wb, Wa, A_log, dt_bias);
    gemm_kernel<<<dim3(ROWS/64, PW/64), 256>>>(x, pWpack, pPack, 256, PW, PW);
    conv_norm_kernel<<<ROWS, 256>>>(qcw, kcw, vcw);
    scan_kernel<<<dim3(64, Bb), 128>>>();
    gate_kernel<<<ROWS, 256>>>(onw);
    gemm_kernel<<<dim3(ROWS/64, 256/64), 256>>>(pO, Wo, out, 256, 256, 256);
}

// round 3
// speedup vs baseline: 3.8289x; 1.6470x over previous
#include <cuda_runtime.h>
#include <math.h>

#define Bb   2
#define Tt   2048
#define ROWS (Bb*Tt)     // 4096
#define PW   1536        // packed width: q|k0|k1|v0|v1|gate

// ---------------- scratch (static device globals; no runtime alloc) ----------------
__device__ float g_Wpack[256 * PW];              // 1.5 MB
__device__ float g_pack[(size_t)ROWS * PW];      // 25.2 MB packed projections
__device__ float g_qn [ROWS * 256];              // normed q
__device__ float g_k0n[ROWS * 256];              // normed k (j=0)
__device__ float g_k1n[ROWS * 256];              // normed k (j=1)
__device__ float g_v  [ROWS * 2 * 256];          // silu'd v (j=0,1)
// per-step scalar record, 12 floats:
// 0 eg, 1 b0, 2 b1, 3 c10=k0.k1, 4 cq0=q.k0, 5 cq1=q.k1,
// 6 g00=k0.k0p, 7 g01=k0.k1p, 8 g10=k1.k0p, 9 g11=k1.k1p, 10 gq0=q.k0p, 11 gq1=q.k1p
__device__ float g_sc [ROWS * 12];
__device__ float g_o  [ROWS * 256];              // scan output, gated in place

// ---------------- weight packing: [256][1536] ----------------
__global__ void pack_weights(const float* __restrict__ Wq, const float* __restrict__ Wk,
                             const float* __restrict__ Wv, const float* __restrict__ Wg)
{
    int d = blockIdx.x, c = threadIdx.x;
    g_Wpack[d*PW + c]        = Wq[d*256 + c];
    g_Wpack[d*PW + 256 + c]  = Wk[d*256 + c];
    g_Wpack[d*PW + 512 + c]  = Wk[65536 + d*256 + c];
    g_Wpack[d*PW + 768 + c]  = Wv[d*256 + c];
    g_Wpack[d*PW + 1024 + c] = Wv[65536 + d*256 + c];
    g_Wpack[d*PW + 1280 + c] = Wg[d*256 + c];
}

// ---------------- fp32 tiled GEMM: C[M,N] = A[M,256] * B[256,N] ----------------
__global__ __launch_bounds__(256)
void gemm_kernel(const float* __restrict__ A, const float* __restrict__ B,
                 float* __restrict__ C, int lda, int ldb, int ldc)
{
    __shared__ float As[32][68];
    __shared__ float Bs[32][64];
    int bm = blockIdx.x * 64, bn = blockIdx.y * 64;
    int tid = threadIdx.x;
    int tx = tid & 15, ty = tid >> 4;
    float acc[4][4] = {};
    for (int k0 = 0; k0 < 256; k0 += 32) {
        #pragma unroll
        for (int i = 0; i < 2; i++) {
            int idx = tid + i*256;
            int ar = idx >> 3, ac = (idx & 7) << 2;
            float4 av = *(const float4*)(A + (size_t)(bm+ar)*lda + k0 + ac);
            As[ac+0][ar] = av.x; As[ac+1][ar] = av.y;
            As[ac+2][ar] = av.z; As[ac+3][ar] = av.w;
            int br = idx >> 4, bc = (idx & 15) << 2;
            *(float4*)(&Bs[br][bc]) = *(const float4*)(B + (size_t)(k0+br)*ldb + bn + bc);
        }
        __syncthreads();
        #pragma unroll
        for (int k = 0; k < 32; k++) {
            float a[4], b[4];
            *(float4*)a = *(const float4*)(&As[k][ty<<2]);
            *(float4*)b = *(const float4*)(&Bs[k][tx<<2]);
            #pragma unroll
            for (int i = 0; i < 4; i++)
                #pragma unroll
                for (int j = 0; j < 4; j++)
                    acc[i][j] = fmaf(a[i], b[j], acc[i][j]);
        }
        __syncthreads();
    }
    #pragma unroll
    for (int i = 0; i < 4; i++)
        *(float4*)(C + (size_t)(bm + (ty<<2) + i)*ldc + bn + (tx<<2)) = *(float4*)acc[i];
}

// ---------------- beta / g projections -> scalar record [0..2] ----------------
__global__ void proj_small(const float* __restrict__ x, const float* __restrict__ Wb,
                           const float* __restrict__ Wa, const float* __restrict__ A_log,
                           const float* __restrict__ dt_bias)
{
    int row  = blockIdx.x * 4 + (threadIdx.x >> 5);
    int lane = threadIdx.x & 31;
    const float* xr = x + (size_t)row * 256;
    float a0 = 0.f, a1 = 0.f, a2 = 0.f;
    #pragma unroll
    for (int r = 0; r < 8; r++) {
        int d = lane + 32*r;
        float xv = xr[d];
        a0 = fmaf(xv, Wb[d],       a0);
        a1 = fmaf(xv, Wb[256 + d], a1);
        a2 = fmaf(xv, Wa[d],       a2);
    }
    #pragma unroll
    for (int off = 16; off; off >>= 1) {
        a0 += __shfl_xor_sync(0xffffffffu, a0, off);
        a1 += __shfl_xor_sync(0xffffffffu, a1, off);
        a2 += __shfl_xor_sync(0xffffffffu, a2, off);
    }
    if (lane == 0) {
        float z  = a2 + dt_bias[0];
        float sp = (z > 20.f) ? z : log1pf(expf(z));
        float g  = -expf(A_log[0]) * sp;
        g_sc[row*12 + 0] = expf(g);                 // eg
        g_sc[row*12 + 1] = 1.f / (1.f + expf(-a0)); // b0
        g_sc[row*12 + 2] = 1.f / (1.f + expf(-a1)); // b1
    }
}

// ---------------- causal conv4 + silu + l2norm + same-step dot scalars ----------------
__global__ __launch_bounds__(256)
void conv_norm_kernel(const float* __restrict__ qw, const float* __restrict__ kw,
                      const float* __restrict__ vw)
{
    int row = blockIdx.x;
    int t   = row & (Tt - 1);
    int c   = threadIdx.x;
    int lane = c & 31, w = c >> 5;
    float acc[5] = {0.f, 0.f, 0.f, 0.f, 0.f};
    #pragma unroll
    for (int i = 0; i < 4; i++) {
        if (t - 3 + i < 0) continue;
        const float* Pr = g_pack + (size_t)(row - 3 + i) * PW;
        acc[0] = fmaf(Pr[c],        qw[c*4 + i],          acc[0]);
        acc[1] = fmaf(Pr[256 + c],  kw[c*4 + i],          acc[1]);
        acc[2] = fmaf(Pr[512 + c],  kw[(256 + c)*4 + i],  acc[2]);
        acc[3] = fmaf(Pr[768 + c],  vw[c*4 + i],          acc[3]);
        acc[4] = fmaf(Pr[1024 + c], vw[(256 + c)*4 + i],  acc[4]);
    }
    #pragma unroll
    for (int m = 0; m < 5; m++) acc[m] = acc[m] / (1.f + expf(-acc[m]));  // silu

    __shared__ float red[3][8];
    float r0 = acc[0]*acc[0], r1 = acc[1]*acc[1], r2 = acc[2]*acc[2];
    #pragma unroll
    for (int off = 16; off; off >>= 1) {
        r0 += __shfl_xor_sync(0xffffffffu, r0, off);
        r1 += __shfl_xor_sync(0xffffffffu, r1, off);
        r2 += __shfl_xor_sync(0xffffffffu, r2, off);
    }
    if (lane == 0) { red[0][w] = r0; red[1][w] = r1; red[2][w] = r2; }
    __syncthreads();
    float s0 = 0.f, s1 = 0.f, s2 = 0.f;
    #pragma unroll
    for (int i = 0; i < 8; i++) { s0 += red[0][i]; s1 += red[1][i]; s2 += red[2][i]; }
    float qv  = acc[0] * rsqrtf(s0 + 1e-6f);
    float k0v = acc[1] * rsqrtf(s1 + 1e-6f);
    float k1v = acc[2] * rsqrtf(s2 + 1e-6f);
    __syncthreads();
    r0 = k0v * k1v; r1 = qv * k0v; r2 = qv * k1v;
    #pragma unroll
    for (int off = 16; off; off >>= 1) {
        r0 += __shfl_xor_sync(0xffffffffu, r0, off);
        r1 += __shfl_xor_sync(0xffffffffu, r1, off);
        r2 += __shfl_xor_sync(0xffffffffu, r2, off);
    }
    if (lane == 0) { red[0][w] = r0; red[1][w] = r1; red[2][w] = r2; }
    __syncthreads();
    s0 = 0.f; s1 = 0.f; s2 = 0.f;
    #pragma unroll
    for (int i = 0; i < 8; i++) { s0 += red[0][i]; s1 += red[1][i]; s2 += red[2][i]; }
    if (c == 0) { g_sc[row*12 + 3] = s0; g_sc[row*12 + 4] = s1; g_sc[row*12 + 5] = s2; }

    g_qn [row*256 + c] = qv;
    g_k0n[row*256 + c] = k0v;
    g_k1n[row*256 + c] = k1v;
    g_v[(size_t)(row*2 + 0)*256 + c] = acc[3];
    g_v[(size_t)(row*2 + 1)*256 + c] = acc[4];
}

// ---------------- adjacent-step Gram scalars -> record [6..11] ----------------
__global__ __launch_bounds__(256)
void gram_kernel()
{
    int row = blockIdx.x;
    int t = row & (Tt - 1);
    int c = threadIdx.x, lane = c & 31, w = c >> 5;
    float qv = 0.f, k0v = 0.f, k1v = 0.f, p0 = 0.f, p1 = 0.f;
    if (t > 0) {
        qv  = g_qn [row*256 + c];
        k0v = g_k0n[row*256 + c];
        k1v = g_k1n[row*256 + c];
        p0  = g_k0n[(row-1)*256 + c];
        p1  = g_k1n[(row-1)*256 + c];
    }
    float r[6] = { k0v*p0, k0v*p1, k1v*p0, k1v*p1, qv*p0, qv*p1 };
    __shared__ float red[6][8];
    #pragma unroll
    for (int off = 16; off; off >>= 1)
        #pragma unroll
        for (int m = 0; m < 6; m++)
            r[m] += __shfl_xor_sync(0xffffffffu, r[m], off);
    if (lane == 0)
        #pragma unroll
        for (int m = 0; m < 6; m++) red[m][w] = r[m];
    __syncthreads();
    if (c < 6) {
        float s = 0.f;
        #pragma unroll
        for (int i = 0; i < 8; i++) s += red[c][i];
        g_sc[row*12 + 6 + c] = s;
    }
}

// ---------------- scan: 1 warp = 1 value-column; reductions pipelined 2 ahead -------
// Serial scalar chain per step t (all lanes redundantly):
//   kS0 = egp*d0 + g00*u0p + g01*u1p        (d* = dots of q/k(t) vs S(t-2))
//   kS1 = egp*d1 + g10*u0p + g11*u1p
//   qS  = egp*dq + gq0*u0p + gq1*u1p
//   u0 = b0*(v0 - eg*kS0); u1 = b1*(v1 - eg*kS1 - c10*u0)
//   o  = eg*qS + cq0*u0 + cq1*u1
//   s  = eg*s + u0*k0(t) + u1*k1(t)
// then compute dots d(t+2) = {q,k0,k1}(t+2) . s  (shuffle result consumed at t+2)
#define LDV(arr, row, dst) do {                                               \
    const float4* _p = (const float4*)(arr + (size_t)(row)*256 + lane*8);     \
    float4 _a = _p[0], _b = _p[1];                                            \
    dst[0]=_a.x; dst[1]=_a.y; dst[2]=_a.z; dst[3]=_a.w;                       \
    dst[4]=_b.x; dst[5]=_b.y; dst[6]=_b.z; dst[7]=_b.w; } while (0)

#define STEP(i) {                                                             \
    const int t = t0 + (i); const int p = (i)&1; const int jb = ((i)+2)&3;    \
    float eg=sc0[p].x, b0v=sc0[p].y, b1v=sc0[p].z, c10=sc0[p].w;              \
    float cq0=sc1[p].x, cq1=sc1[p].y, g00=sc1[p].z, g01=sc1[p].w;             \
    float g10=sc2[p].x, g11=sc2[p].y, gq0=sc2[p].z, gq1=sc2[p].w;             \
    float kS0 = fmaf(egp, d0[p], fmaf(g00, u0p, g01*u1p));                    \
    float kS1 = fmaf(egp, d1[p], fmaf(g10, u0p, g11*u1p));                    \
    float qS  = fmaf(egp, dq[p], fmaf(gq0, u0p, gq1*u1p));                    \
    float u0 = b0v * fmaf(-eg, kS0, vv0[p]);                                  \
    float u1 = b1v * (vv1[p] - eg*kS1 - c10*u0);                              \
    float ov = fmaf(eg, qS, fmaf(cq0, u0, cq1*u1));                           \
    if (lane == 0) g_o[(size_t)(base + t)*256 + col] = ov;                    \
    _Pragma("unroll")                                                         \
    for (int r = 0; r < 8; r++)                                               \
        s[r] = fmaf(k1b[i][r], u1, fmaf(k0b[i][r], u0, eg*s[r]));             \
    u0p = u0; u1p = u1; egp = eg;                                             \
    {   int rl = base + ((t+4 < Tt) ? (t+4) : (Tt-1));                        \
        LDV(g_qn, rl, qb[i]); LDV(g_k0n, rl, k0b[i]); LDV(g_k1n, rl, k1b[i]); \
        int rs = base + ((t+2 < Tt) ? (t+2) : (Tt-1));                        \
        sc0[p] = *(const float4*)(g_sc + (size_t)rs*12);                      \
        sc1[p] = *(const float4*)(g_sc + (size_t)rs*12 + 4);                  \
        sc2[p] = *(const float4*)(g_sc + (size_t)rs*12 + 8);                  \
        vv0[p] = g_v[(size_t)rs*512 + col];                                   \
        vv1[p] = g_v[(size_t)rs*512 + 256 + col]; }                           \
    float m0a=0.f,m0b=0.f,m1a=0.f,m1b=0.f,mqa=0.f,mqb=0.f;                    \
    _Pragma("unroll")                                                         \
    for (int r = 0; r < 8; r += 2) {                                          \
        m0a = fmaf(s[r],   k0b[jb][r],   m0a);                                \
        m0b = fmaf(s[r+1], k0b[jb][r+1], m0b);                                \
        m1a = fmaf(s[r],   k1b[jb][r],   m1a);                                \
        m1b = fmaf(s[r+1], k1b[jb][r+1], m1b);                                \
        mqa = fmaf(s[r],   qb[jb][r],    mqa);                                \
        mqb = fmaf(s[r+1], qb[jb][r+1],  mqb); }                              \
    float m0_ = m0a+m0b, m1_ = m1a+m1b, mq_ = mqa+mqb;                        \
    _Pragma("unroll")                                                         \
    for (int off = 16; off; off >>= 1) {                                      \
        m0_ += __shfl_xor_sync(0xffffffffu, m0_, off);                        \
        m1_ += __shfl_xor_sync(0xffffffffu, m1_, off);                        \
        mq_ += __shfl_xor_sync(0xffffffffu, mq_, off); }                      \
    d0[p] = m0_; d1[p] = m1_; dq[p] = mq_;                                    \
}

__global__ __launch_bounds__(128)
void scan_kernel()
{
    int b    = blockIdx.y;
    int lane = threadIdx.x & 31;
    int col  = blockIdx.x * 4 + (threadIdx.x >> 5);   // 0..255
    int base = b * Tt;

    float s[8];
    #pragma unroll
    for (int r = 0; r < 8; r++) s[r] = 0.f;

    float qb[4][8], k0b[4][8], k1b[4][8];
    float4 sc0[2], sc1[2], sc2[2];
    float vv0[2], vv1[2];
    float dq[2] = {0.f, 0.f}, d0[2] = {0.f, 0.f}, d1[2] = {0.f, 0.f};
    float u0p = 0.f, u1p = 0.f, egp = 0.f;

    #pragma unroll
    for (int i = 0; i < 4; i++) {
        int row = base + i;
        LDV(g_qn, row, qb[i]); LDV(g_k0n, row, k0b[i]); LDV(g_k1n, row, k1b[i]);
    }
    #pragma unroll
    for (int p = 0; p < 2; p++) {
        int row = base + p;
        sc0[p] = *(const float4*)(g_sc + (size_t)row*12);
        sc1[p] = *(const float4*)(g_sc + (size_t)row*12 + 4);
        sc2[p] = *(const float4*)(g_sc + (size_t)row*12 + 8);
        vv0[p] = g_v[(size_t)row*512 + col];
        vv1[p] = g_v[(size_t)row*512 + 256 + col];
    }

    for (int t0 = 0; t0 < Tt; t0 += 4) {
        STEP(0) STEP(1) STEP(2) STEP(3)
    }
}

// ---------------- output rms-norm * o_norm_w * silu(gate), in place ----------------
__global__ __launch_bounds__(256)
void gate_kernel(const float* __restrict__ onw)
{
    int row = blockIdx.x, c = threadIdx.x;
    int lane = c & 31, w = c >> 5;
    float ov = g_o[(size_t)row*256 + c];
    float r = ov * ov;
    __shared__ float red[8];
    #pragma unroll
    for (int off = 16; off; off >>= 1) r += __shfl_xor_sync(0xffffffffu, r, off);
    if (lane == 0) red[w] = r;
    __syncthreads();
    float sum = 0.f;
    #pragma unroll
    for (int i = 0; i < 8; i++) sum += red[i];
    float gt  = g_pack[(size_t)row*PW + 1280 + c];
    float res = ov * rsqrtf(sum * (1.f/256.f) + 1e-5f) * onw[c] * (gt / (1.f + expf(-gt)));
    g_o[(size_t)row*256 + c] = res;
}

// ---------------- launch ----------------
extern "C" void kernel_launch(void* const* d_in, const int* in_sizes, int n_in,
                              void* d_out, int out_size)
{
    const float* x       = (const float*)d_in[0];
    const float* Wq      = (const float*)d_in[1];
    const float* Wk      = (const float*)d_in[2];
    const float* Wv      = (const float*)d_in[3];
    const float* Wb      = (const float*)d_in[4];
    const float* Wa      = (const float*)d_in[5];
    const float* A_log   = (const float*)d_in[6];
    const float* dt_bias = (const float*)d_in[7];
    const float* qcw     = (const float*)d_in[8];
    const float* kcw     = (const float*)d_in[9];
    const float* vcw     = (const float*)d_in[10];
    const float* Wg      = (const float*)d_in[11];
    const float* onw     = (const float*)d_in[12];
    const float* Wo      = (const float*)d_in[13];
    float* out = (float*)d_out;

    float *pWpack, *pPack, *pO;
    cudaGetSymbolAddress((void**)&pWpack, g_Wpack);
    cudaGetSymbolAddress((void**)&pPack,  g_pack);
    cudaGetSymbolAddress((void**)&pO,     g_o);

    pack_weights<<<256, 256>>>(Wq, Wk, Wv, Wg);
    proj_small<<<ROWS/4, 128>>>(x, Wb, Wa, A_log, dt_bias);
    gemm_kernel<<<dim3(ROWS/64, PW/64), 256>>>(x, pWpack, pPack, 256, PW, PW);
    conv_norm_kernel<<<ROWS, 256>>>(qcw, kcw, vcw);
    gram_kernel<<<ROWS, 256>>>();
    scan_kernel<<<dim3(64, Bb), 128>>>();
    gate_kernel<<<ROWS, 256>>>(onw);
    gemm_kernel<<<dim3(ROWS/64, 256/64), 256>>>(pO, Wo, out, 256, 256, 256);
}